// round 5
// baseline (speedup 1.0000x reference)
#include <cuda_runtime.h>
#include <float.h>
#include <math.h>
#include <stdint.h>

#define BB 8
#define DD 256
#define MEMN 131072
#define CWN 64
#define RR 4
#define KK 4
#define TKL 8
#define CC 25
#define DELTA_F 0.005f
#define EPS_F 1e-6f

#define SCAN_NBLK 16
#define SCAN_ROWS (MEMN / SCAN_NBLK)   // 8192
#define TILE_ROWS 256
#define NT (SCAN_ROWS / TILE_ROWS)     // 32
#define ROW_F4 17                      // padded float4 per row (272 B)
#define TILE_F4 (TILE_ROWS * ROW_F4)   // 4352
#define BUF_BYTES (2 * TILE_F4 * 16)   // 139264
#define QSM_OFF   BUF_BYTES            // 139264 (1024 B)
#define SROW_OFF  (QSM_OFF + 1024)     // 140288 (128 B)
#define NS_OFF    (SROW_OFF + 128)     // 140416
#define SMEM_BYTES 140544

#define UMB 16
#define UMCH (MEMN / UMB)              // 8192

// ---------------- device scratch ----------------
__device__ float g_q[BB][DD];
__device__ float g_visnew[BB][CC][CWN];
__device__ float g_relnew[BB][CC];
__device__ int   g_fp[BB][KK];
__device__ int   g_bp[BB][KK];
__device__ float g_bv[BB][RR][SCAN_NBLK][KK];
__device__ int   g_bi[BB][RR][SCAN_NBLK][KK];
__device__ float g_uv[UMB];
__device__ int   g_ui[UMB];

// ---------------- helpers ----------------
__device__ __forceinline__ void ins4s(float s, int m,
    float &v0, int &i0, float &v1, int &i1,
    float &v2, int &i2, float &v3, int &i3)
{
    if (!((s > v3) || (s == v3 && m < i3))) return;
    v3 = s; i3 = m;
    if ((v3 > v2) || (v3 == v2 && i3 < i2)) { float tv=v2; int ti=i2; v2=v3; i2=i3; v3=tv; i3=ti; }
    if ((v2 > v1) || (v2 == v1 && i2 < i1)) { float tv=v1; int ti=i1; v1=v2; i1=i2; v2=tv; i2=ti; }
    if ((v1 > v0) || (v1 == v0 && i1 < i0)) { float tv=v0; int ti=i0; v0=v1; i0=i1; v1=tv; i1=ti; }
}

struct Top4 { float v0, v1, v2, v3; int i0, i1, i2, i3; };
__device__ __forceinline__ void t4init(Top4 &t) {
    t.v0 = t.v1 = t.v2 = t.v3 = -FLT_MAX;
    t.i0 = t.i1 = t.i2 = t.i3 = 0x7fffffff;
}
__device__ __forceinline__ void t4ins(Top4 &t, float s, int m) {
    ins4s(s, m, t.v0, t.i0, t.v1, t.i1, t.v2, t.i2, t.v3, t.i3);
}

__device__ __forceinline__ float sig_(float x) { return 1.f / (1.f + expf(-x)); }

__device__ __forceinline__ void cpa16(uint32_t dst, const void* src) {
    asm volatile("cp.async.cg.shared.global [%0], [%1], 16;" :: "r"(dst), "l"(src));
}
__device__ __forceinline__ uint32_t smem_u32(const void* p) {
    return (uint32_t)__cvta_generic_to_shared(p);
}

// ============================================================================
// K1: all projections on disjoint concurrent thread ranges + state updates +
//     link diagonals + fp/bp. 1 block/batch, 1024 threads.
// ============================================================================
__global__ void __launch_bounds__(1024) k1_setup(
    const float* __restrict__ xi,
    const float* __restrict__ visible_memory,
    const float* __restrict__ link_matrix,
    const float* __restrict__ rev_link_matrix,
    const float* __restrict__ precedence,
    const float* __restrict__ read_weights,
    const float* __restrict__ write_weights,
    const float* __restrict__ usage,
    const int*   __restrict__ read_positions,
    const float* __restrict__ W_rq, const float* __restrict__ b_rq,
    const float* __restrict__ W_wv, const float* __restrict__ b_wv,
    const float* __restrict__ W_ig, const float* __restrict__ b_ig,
    const float* __restrict__ W_wg, const float* __restrict__ b_wg)
{
    int b = blockIdx.x;
    int t = threadIdx.x;

    __shared__ float xs[DD];
    __shared__ float prq[2][DD];
    __shared__ float pwv[2][CWN];
    __shared__ float pig[4][CC];
    __shared__ float pwg[32];
    __shared__ float wv_s[CWN];
    __shared__ float ig_s[CC];
    __shared__ float wg_s;
    __shared__ int   rp_s[CC];
    __shared__ float rw_s[CC], rel_s[CC], u_s[CC], imin_s[CC], wwnew_s[CC];
    __shared__ float minrel_s;
    __shared__ float fw_s[TKL], bw_s[TKL];

    if (t < DD) xs[t] = xi[b * DD + t];
    if (t >= 256 && t < 256 + CC) rp_s[t - 256] = read_positions[b * CC + (t - 256)];
    __syncthreads();

    if (t < 512) {
        // Phase A: rq, 2-way d split (128 d per thread)
        int o = t & 255, c = t >> 8;
        const float* W = W_rq + (size_t)(c * 128) * 256 + o;
        const float* x = xs + c * 128;
        float a0=0.f,a1=0.f,a2=0.f,a3=0.f,a4=0.f,a5=0.f,a6=0.f,a7=0.f;
        #pragma unroll 16
        for (int d = 0; d < 128; d += 8) {
            a0 = fmaf(x[d+0], W[(d+0)*256], a0);
            a1 = fmaf(x[d+1], W[(d+1)*256], a1);
            a2 = fmaf(x[d+2], W[(d+2)*256], a2);
            a3 = fmaf(x[d+3], W[(d+3)*256], a3);
            a4 = fmaf(x[d+4], W[(d+4)*256], a4);
            a5 = fmaf(x[d+5], W[(d+5)*256], a5);
            a6 = fmaf(x[d+6], W[(d+6)*256], a6);
            a7 = fmaf(x[d+7], W[(d+7)*256], a7);
        }
        prq[c][o] = ((a0+a1)+(a2+a3)) + ((a4+a5)+(a6+a7));
    } else if (t < 640) {
        // Phase B: wv, 2-way d split
        int u = t - 512, o = u & 63, c = u >> 6;
        const float* W = W_wv + (size_t)(c * 128) * CWN + o;
        const float* x = xs + c * 128;
        float a0=0.f,a1=0.f,a2=0.f,a3=0.f;
        #pragma unroll 8
        for (int d = 0; d < 128; d += 4) {
            a0 = fmaf(x[d+0], W[(d+0)*CWN], a0);
            a1 = fmaf(x[d+1], W[(d+1)*CWN], a1);
            a2 = fmaf(x[d+2], W[(d+2)*CWN], a2);
            a3 = fmaf(x[d+3], W[(d+3)*CWN], a3);
        }
        pwv[c][o] = (a0+a1)+(a2+a3);
    } else if (t < 740) {
        // Phase C: ig, 4-way d split
        int u = t - 640, o = u % CC, c = u / CC;
        const float* W = W_ig + (size_t)(c * 64) * CC + o;
        const float* x = xs + c * 64;
        float a0=0.f,a1=0.f,a2=0.f,a3=0.f;
        #pragma unroll 4
        for (int d = 0; d < 64; d += 4) {
            a0 = fmaf(x[d+0], W[(d+0)*CC], a0);
            a1 = fmaf(x[d+1], W[(d+1)*CC], a1);
            a2 = fmaf(x[d+2], W[(d+2)*CC], a2);
            a3 = fmaf(x[d+3], W[(d+3)*CC], a3);
        }
        pig[c][o] = (a0+a1)+(a2+a3);
    } else if (t < 772) {
        // Phase D: wg, 32-way
        int u = t - 740;
        float a = 0.f;
        #pragma unroll
        for (int d = 0; d < 8; d++)
            a = fmaf(xs[u*8+d], __ldg(&W_wg[u*8+d]), a);
        pwg[u] = a;
    } else if (t < 772 + CC) {
        // Phase E: scattered state gather
        int c = t - 772;
        int p = rp_s[c];
        float rw  = __ldg(&read_weights [(size_t)b * MEMN + p]);
        float ww  = __ldg(&write_weights[(size_t)b * MEMN + p]);
        float rel = __ldg(&usage        [(size_t)b * MEMN + p]);
        rw_s[c]  = rw;
        rel_s[c] = rel;
        u_s[c]   = (rw + ww > DELTA_F) ? 1.f : 0.f;
    }
    __syncthreads();

    // combine partials
    if (t < DD) {
        g_q[b][t] = b_rq[t] + prq[0][t] + prq[1][t];
    } else if (t < DD + CWN) {
        int o = t - DD;
        wv_s[o] = b_wv[o] + pwv[0][o] + pwv[1][o];
    } else if (t < DD + CWN + CC) {
        int o = t - DD - CWN;
        ig_s[o] = sig_(b_ig[o] + ((pig[0][o] + pig[1][o]) + (pig[2][o] + pig[3][o])));
    } else if (t == DD + CWN + CC) {
        float s = b_wg[0];
        #pragma unroll
        for (int u = 0; u < 32; u++) s += pwg[u];
        wg_s = sig_(s);
    } else if (t == 346) {
        float mn = rel_s[0];
        for (int c = 1; c < CC; c++) mn = fminf(mn, rel_s[c]);
        minrel_s = mn;
    }
    __syncthreads();

    if (t < CC) {
        float Imin = (rel_s[t] == minrel_s) ? 1.f : 0.f;
        imin_s[t] = Imin;
        float u = u_s[t], rel = rel_s[t];
        g_relnew[b][t] = (1.f - rel) * u + rel * (1.f - u);
        wwnew_s[t] = wg_s * (ig_s[t] * rw_s[t] + (1.f - ig_s[t]) * Imin);
    }
    __syncthreads();

    for (int e = t; e < CC * CWN; e += blockDim.x) {
        int c = e / CWN, k = e % CWN;
        float v = visible_memory[((size_t)b * CC + c) * CWN + k];
        g_visnew[b][c][k] = v * (1.f - imin_s[c]) + wwnew_s[c] * wv_s[k];
    }

    if (t < TKL) {
        int m = t;
        float wwf = __ldg(&write_weights[(size_t)b * MEMN + m]);
        for (int c = 0; c < CC; c++) if (rp_s[c] == m) wwf = wwnew_s[c];
        int tp = rp_s[RR * KK + m];
        float tw = __ldg(&write_weights[(size_t)b * MEMN + tp]);
        for (int c = 0; c < CC; c++) if (rp_s[c] == tp) tw = wwnew_s[c];
        float pd = 0.f;
        for (int j = 0; j < TKL; j++)
            if (rp_s[RR * KK + j] == m) pd = __ldg(&precedence[b * TKL + j]);
        float trw = __ldg(&read_weights[(size_t)b * MEMN + tp]);
        float Ld = (1.f - wwf) * __ldg(&link_matrix    [((size_t)b * MEMN + m) * TKL + m])
                 + wwf * __ldg(&precedence[b * TKL + m]);
        float Rd = (1.f - tw ) * __ldg(&rev_link_matrix[((size_t)b * MEMN + m) * TKL + m])
                 + tw  * pd;
        fw_s[m] = Ld * trw;
        bw_s[m] = Rd * trw;
    }
    __syncthreads();

    if (t == 0) {
        bool used[TKL];
        for (int m = 0; m < TKL; m++) used[m] = false;
        for (int k = 0; k < KK; k++) {
            int best = -1;
            for (int m = 0; m < TKL; m++)
                if (!used[m] && (best < 0 || fw_s[m] > fw_s[best])) best = m;
            used[best] = true;
            g_fp[b][k] = best;
        }
        for (int m = 0; m < TKL; m++) used[m] = false;
        for (int k = 0; k < KK; k++) {
            int best = -1;
            for (int m = 0; m < TKL; m++)
                if (!used[m] && (best < 0 || bw_s[m] > bw_s[best])) best = m;
            used[best] = true;
            g_bp[b][k] = best;
        }
    }
}

// ============================================================================
// K2: cp.async double-buffered smem-staged scan — no shuffles.
//     128 scan blocks (8192 rows each) + 16 usage-argmin blocks = 1 wave.
// ============================================================================
extern __shared__ __align__(16) char k2sm[];

__global__ void __launch_bounds__(256) k2_scan(
    const float* __restrict__ memv,
    const float* __restrict__ usage,
    const int*   __restrict__ rp)
{
    int t = threadIdx.x;

    if (blockIdx.x >= BB * SCAN_NBLK) {
        // ---- usage argmin for batch 0 (read positions masked out) ----
        int ib = blockIdx.x - BB * SCAN_NBLK;
        int*   rp0 = (int*)k2sm;
        float* svv = (float*)(k2sm + 128);
        int*   sii = (int*)(k2sm + 128 + 1024);
        if (t < CC) rp0[t] = rp[t];
        __syncthreads();
        float bv = FLT_MAX; int bi = 0x7fffffff;
        int base = ib * UMCH;
        for (int j = t; j < UMCH; j += 256) {
            int idx = base + j;
            float v = __ldcs(&usage[idx]);
            bool masked = false;
            #pragma unroll
            for (int c = 0; c < CC; c++) masked |= (rp0[c] == idx);
            if (!masked && (v < bv || (v == bv && idx < bi))) { bv = v; bi = idx; }
        }
        svv[t] = bv; sii[t] = bi;
        __syncthreads();
        for (int s = 128; s > 0; s >>= 1) {
            if (t < s) {
                if (svv[t+s] < svv[t] || (svv[t+s] == svv[t] && sii[t+s] < sii[t])) {
                    svv[t] = svv[t+s]; sii[t] = sii[t+s];
                }
            }
            __syncthreads();
        }
        if (t == 0) { g_uv[ib] = svv[0]; g_ui[ib] = sii[0]; }
        return;
    }

    int b   = blockIdx.x / SCAN_NBLK;
    int blk = blockIdx.x % SCAN_NBLK;
    int rowbase = blk * SCAN_ROWS;

    float4* buf  = (float4*)k2sm;                     // 2 tiles
    float4* qsm4 = (float4*)(k2sm + QSM_OFF);         // 4x16 float4
    int*    srow = (int*)(k2sm + SROW_OFF);
    int*    nsp  = (int*)(k2sm + NS_OFF);

    if (t == 0) *nsp = 0;
    if (t < 64) qsm4[t] = ((const float4*)&g_q[b][0])[t];
    __syncthreads();
    if (t < CC) {
        int p = rp[b * CC + t];
        if (p >= rowbase && p < rowbase + SCAN_ROWS) {
            int k = atomicAdd(nsp, 1);
            srow[k] = p;
        }
    }
    __syncthreads();
    int nspec = *nsp;

    const char* gsrc = (const char*)(memv + ((size_t)b * MEMN + rowbase) * CWN);

    // prologue: load tiles 0 and 1
    #pragma unroll
    for (int T = 0; T < 2; T++) {
        uint32_t dbase = smem_u32(buf + (size_t)T * TILE_F4);
        const char* src = gsrc + (size_t)T * TILE_ROWS * 256;
        #pragma unroll
        for (int j = 0; j < 16; j++) {
            int g = t + j * 256;
            int row = g >> 4, pos = g & 15;
            cpa16(dbase + (uint32_t)(row * ROW_F4 + pos) * 16, src + (size_t)g * 16);
        }
        asm volatile("cp.async.commit_group;");
    }

    Top4 tk0, tk1, tk2, tk3;
    t4init(tk0); t4init(tk1); t4init(tk2); t4init(tk3);

    for (int T = 0; T < NT; T++) {
        if (T + 2 < NT) { asm volatile("cp.async.wait_group 1;"); }
        else            { asm volatile("cp.async.wait_group 0;"); }
        __syncthreads();

        const float4* rowp = buf + (size_t)(T & 1) * TILE_F4 + t * ROW_F4;
        float sq = 0.f, d0 = 0.f, d1 = 0.f, d2 = 0.f, d3 = 0.f;
        #pragma unroll
        for (int i = 0; i < 16; i++) {
            float4 a  = rowp[i];
            float4 q0 = qsm4[i];
            float4 q1 = qsm4[16 + i];
            float4 q2 = qsm4[32 + i];
            float4 q3 = qsm4[48 + i];
            sq = fmaf(a.x, a.x, sq);  sq = fmaf(a.y, a.y, sq);
            sq = fmaf(a.z, a.z, sq);  sq = fmaf(a.w, a.w, sq);
            d0 = fmaf(a.x, q0.x, d0); d0 = fmaf(a.y, q0.y, d0);
            d0 = fmaf(a.z, q0.z, d0); d0 = fmaf(a.w, q0.w, d0);
            d1 = fmaf(a.x, q1.x, d1); d1 = fmaf(a.y, q1.y, d1);
            d1 = fmaf(a.z, q1.z, d1); d1 = fmaf(a.w, q1.w, d1);
            d2 = fmaf(a.x, q2.x, d2); d2 = fmaf(a.y, q2.y, d2);
            d2 = fmaf(a.z, q2.z, d2); d2 = fmaf(a.w, q2.w, d2);
            d3 = fmaf(a.x, q3.x, d3); d3 = fmaf(a.y, q3.y, d3);
            d3 = fmaf(a.z, q3.z, d3); d3 = fmaf(a.w, q3.w, d3);
        }
        int grow = rowbase + T * TILE_ROWS + t;
        bool masked = false;
        for (int j = 0; j < nspec; j++) masked |= (srow[j] == grow);
        if (!masked) {
            t4ins(tk0, 2.f * d0 - sq, grow);
            t4ins(tk1, 2.f * d1 - sq, grow);
            t4ins(tk2, 2.f * d2 - sq, grow);
            t4ins(tk3, 2.f * d3 - sq, grow);
        }
        __syncthreads();   // all done reading buf[T&1] before reloading it

        if (T + 2 < NT) {
            uint32_t dbase = smem_u32(buf + (size_t)(T & 1) * TILE_F4);
            const char* src = gsrc + (size_t)(T + 2) * TILE_ROWS * 256;
            #pragma unroll
            for (int j = 0; j < 16; j++) {
                int g = t + j * 256;
                int row = g >> 4, pos = g & 15;
                cpa16(dbase + (uint32_t)(row * ROW_F4 + pos) * 16, src + (size_t)g * 16);
            }
            asm volatile("cp.async.commit_group;");
        }
    }
    __syncthreads();

    // ---- block merge (overlay on buf region) ----
    float* mv  = (float*)k2sm;             // [4][256][4]
    int*   mi  = (int*)(k2sm + 16384);     // [4][256][4]
    float* mv2 = (float*)(k2sm + 32768);   // [4][32][4]
    int*   mi2 = (int*)(k2sm + 34816);
    float* mv3 = (float*)(k2sm + 36864);   // [4][4][4]
    int*   mi3 = (int*)(k2sm + 37120);

    {
        Top4* tks[4] = { &tk0, &tk1, &tk2, &tk3 };
        #pragma unroll
        for (int r = 0; r < RR; r++) {
            Top4 &x = *tks[r];
            int o = r * 1024 + t * 4;
            mv[o+0] = x.v0; mi[o+0] = x.i0;
            mv[o+1] = x.v1; mi[o+1] = x.i1;
            mv[o+2] = x.v2; mi[o+2] = x.i2;
            mv[o+3] = x.v3; mi[o+3] = x.i3;
        }
    }
    __syncthreads();

    if (t < 128) {  // stage 1: 32 workers per r, 32 entries each
        int r = t >> 5, w = t & 31;
        Top4 x; t4init(x);
        for (int s = w * 8; s < w * 8 + 8; s++)
            for (int k = 0; k < 4; k++)
                t4ins(x, mv[r*1024 + s*4 + k], mi[r*1024 + s*4 + k]);
        int o = r * 128 + w * 4;
        mv2[o+0] = x.v0; mi2[o+0] = x.i0;
        mv2[o+1] = x.v1; mi2[o+1] = x.i1;
        mv2[o+2] = x.v2; mi2[o+2] = x.i2;
        mv2[o+3] = x.v3; mi2[o+3] = x.i3;
    }
    __syncthreads();
    if (t < 16) {   // stage 2: 4 workers per r, 32 entries each
        int r = t >> 2, w = t & 3;
        Top4 x; t4init(x);
        for (int s = w * 8; s < w * 8 + 8; s++)
            for (int k = 0; k < 4; k++)
                t4ins(x, mv2[r*128 + s*4 + k], mi2[r*128 + s*4 + k]);
        int o = r * 16 + w * 4;
        mv3[o+0] = x.v0; mi3[o+0] = x.i0;
        mv3[o+1] = x.v1; mi3[o+1] = x.i1;
        mv3[o+2] = x.v2; mi3[o+2] = x.i2;
        mv3[o+3] = x.v3; mi3[o+3] = x.i3;
    }
    __syncthreads();
    if (t < RR) {   // stage 3
        Top4 x; t4init(x);
        for (int j = 0; j < 16; j++)
            t4ins(x, mv3[t*16 + j], mi3[t*16 + j]);
        g_bv[b][t][blk][0] = x.v0; g_bi[b][t][blk][0] = x.i0;
        g_bv[b][t][blk][1] = x.v1; g_bi[b][t][blk][1] = x.i1;
        g_bv[b][t][blk][2] = x.v2; g_bi[b][t][blk][2] = x.i2;
        g_bv[b][t][blk][3] = x.v3; g_bi[b][t][blk][3] = x.i3;
    }
}

// ============================================================================
// K3: global merge + fp/bp/lum + clip + gather + cosine softmax read.
// ============================================================================
__global__ void __launch_bounds__(256) k3_finish(
    const float* __restrict__ memv,
    const int*   __restrict__ rp,
    float* __restrict__ out)
{
    int b = blockIdx.x;
    int t = threadIdx.x;

    __shared__ float q[RR][CWN];
    __shared__ float kq[RR][CWN];
    __shared__ float qn[RR];
    __shared__ int   rps[CC];
    __shared__ int   valid[CC];
    __shared__ float specs[RR][CC];
    __shared__ float cv[RR][SCAN_NBLK * KK];
    __shared__ int   ci[RR][SCAN_NBLK * KK];
    __shared__ int   pos[CC];
    __shared__ int   maxlen_s;
    __shared__ int   rowsrc[CC];
    __shared__ float vis[CC][CWN];
    __shared__ float vinv[CC];
    __shared__ float sim[RR][CC];
    __shared__ float sw[RR][CC];

    q[t >> 6][t & 63] = g_q[b][t];
    __syncthreads();

    if (t < RR) {
        float s = 0.f;
        for (int wc = 0; wc < CWN; wc++) s = fmaf(q[t][wc], q[t][wc], s);
        qn[t] = 1.f / (sqrtf(s) + EPS_F);
    }
    if (t >= 32 && t < 32 + CC) rps[t - 32] = rp[b * CC + (t - 32)];
    if (t < RR * SCAN_NBLK * KK) {
        int r = t / (SCAN_NBLK * KK), j = t % (SCAN_NBLK * KK);
        cv[r][j] = (&g_bv[b][r][0][0])[j];
        ci[r][j] = (&g_bi[b][r][0][0])[j];
    }
    __syncthreads();

    kq[t >> 6][t & 63] = q[t >> 6][t & 63] * qn[t >> 6];
    if (t < CC) {
        int v = 1;
        for (int c = t + 1; c < CC; c++) if (rps[c] == rps[t]) v = 0;
        valid[t] = v;
    }
    if (t >= 128 && t < 128 + RR * CC) {
        int e = t - 128;
        int c = e / RR, r = e % RR;
        float dt = 0.f, sq = 0.f;
        for (int wc = 0; wc < CWN; wc++) {
            float m = g_visnew[b][c][wc];
            dt = fmaf(q[r][wc], m, dt);
            sq = fmaf(m, m, sq);
        }
        specs[r][c] = 2.f * dt - sq;
    }
    if (t == 255) {
        float bv = FLT_MAX; int bi = 0x7fffffff;
        for (int i = 0; i < UMB; i++) {
            float v = g_uv[i]; int ix = g_ui[i];
            if (v < bv || (v == bv && ix < bi)) { bv = v; bi = ix; }
        }
        for (int c = 0; c < CC; c++) {
            int p0 = rp[c];
            int last = 1;
            for (int c2 = c + 1; c2 < CC; c2++) if (rp[c2] == p0) last = 0;
            if (!last) continue;
            float v = g_relnew[0][c];
            if (v < bv || (v == bv && p0 < bi)) { bv = v; bi = p0; }
        }
        maxlen_s = bi;
    }
    __syncthreads();

    if (t < RR) {
        float v0 = -FLT_MAX, v1 = -FLT_MAX, v2 = -FLT_MAX, v3 = -FLT_MAX;
        int   i0 = 0x7fffffff, i1 = 0x7fffffff, i2 = 0x7fffffff, i3 = 0x7fffffff;
        for (int j = 0; j < SCAN_NBLK * KK; j++)
            ins4s(cv[t][j], ci[t][j], v0, i0, v1, i1, v2, i2, v3, i3);
        for (int c = 0; c < CC; c++)
            if (valid[c]) ins4s(specs[t][c], rps[c], v0, i0, v1, i1, v2, i2, v3, i3);
        pos[t * 4 + 0] = i0; pos[t * 4 + 1] = i1; pos[t * 4 + 2] = i2; pos[t * 4 + 3] = i3;
    }
    if (t == 4) {
        for (int k = 0; k < KK; k++) { pos[16 + k] = g_fp[b][k]; pos[20 + k] = g_bp[b][k]; }
        pos[24] = CC + 1;
    }
    __syncthreads();

    if (t < CC) {
        int p = pos[t];
        int ml = maxlen_s;
        p = p < 0 ? 0 : (p > ml ? ml : p);
        pos[t] = p;
        int s = -1;
        for (int c = 0; c < CC; c++) if (rps[c] == p) s = c;
        rowsrc[t] = s;
    }
    __syncthreads();

    for (int e = t; e < CC * CWN; e += 256) {
        int c = e / CWN, wc = e % CWN;
        int s = rowsrc[c];
        vis[c][wc] = (s >= 0) ? g_visnew[b][s][wc]
                              : memv[((size_t)b * MEMN + pos[c]) * CWN + wc];
    }
    __syncthreads();

    if (t < CC) {
        float s = 0.f;
        for (int wc = 0; wc < CWN; wc++) s = fmaf(vis[t][wc], vis[t][wc], s);
        vinv[t] = 1.f / (sqrtf(s) + EPS_F);
    }
    __syncthreads();

    if (t < RR * CC) {
        int r = t / CC, c = t % CC;
        float s = 0.f;
        for (int wc = 0; wc < CWN; wc++) s = fmaf(kq[r][wc], vis[c][wc], s);
        sim[r][c] = s * vinv[c];
    }
    __syncthreads();

    if (t < RR) {
        float mx = -FLT_MAX;
        for (int c = 0; c < CC; c++) mx = fmaxf(mx, sim[t][c]);
        float sum = 0.f;
        for (int c = 0; c < CC; c++) { float e = expf(sim[t][c] - mx); sw[t][c] = e; sum += e; }
        float inv = 1.f / sum;
        for (int c = 0; c < CC; c++) sw[t][c] *= inv;
    }
    __syncthreads();

    {
        int r = t >> 6, wc = t & 63;
        float o = 0.f;
        for (int c = 0; c < CC; c++) o = fmaf(sw[r][c], vis[c][wc], o);
        out[b * RR * CWN + t] = o;
    }
}

// ============================================================================
extern "C" void kernel_launch(void* const* d_in, const int* in_sizes, int n_in,
                              void* d_out, int out_size) {
    const float* xi       = (const float*)d_in[0];
    const float* memory   = (const float*)d_in[1];
    const float* vism     = (const float*)d_in[2];
    const float* linkm    = (const float*)d_in[3];
    const float* rlinkm   = (const float*)d_in[4];
    const float* prec     = (const float*)d_in[5];
    const float* rw       = (const float*)d_in[6];
    const float* ww       = (const float*)d_in[7];
    const float* usage    = (const float*)d_in[8];
    const int*   rp       = (const int*)d_in[10];
    const float* W_rq     = (const float*)d_in[11];
    const float* b_rq     = (const float*)d_in[12];
    const float* W_wv     = (const float*)d_in[13];
    const float* b_wv     = (const float*)d_in[14];
    const float* W_ig     = (const float*)d_in[15];
    const float* b_ig     = (const float*)d_in[16];
    const float* W_wg     = (const float*)d_in[17];
    const float* b_wg     = (const float*)d_in[18];
    float* out = (float*)d_out;

    static bool attr_set = false;
    if (!attr_set) {
        cudaFuncSetAttribute(k2_scan, cudaFuncAttributeMaxDynamicSharedMemorySize,
                             SMEM_BYTES);
        attr_set = true;
    }

    k1_setup<<<BB, 1024>>>(xi, vism, linkm, rlinkm, prec, rw, ww, usage, rp,
                           W_rq, b_rq, W_wv, b_wv, W_ig, b_ig, W_wg, b_wg);
    k2_scan<<<BB * SCAN_NBLK + UMB, 256, SMEM_BYTES>>>(memory, usage, rp);
    k3_finish<<<BB, 256>>>(memory, rp, out);
}